// round 1
// baseline (speedup 1.0000x reference)
#include <cuda_runtime.h>
#include <cuda_bf16.h>
#include <math.h>

#define NN 100000
#define EE 400000
#define GG 64
#define HD 256

// ---------------- scratch (device globals; no allocation allowed) ----------------
__device__ float g_h0[NN * 64];        // encoder output
__device__ float g_xl[NN * HD];        // source-side transform
__device__ float g_xr[NN * HD];        // target-side transform
__device__ float g_acc[NN * HD];       // attention-weighted scatter accumulator
__device__ float g_h1[NN * HD];        // layer output (relu(acc+bias))
__device__ float g_logit[EE * 4];      // per-edge per-head logit, then exp
__device__ float g_m[NN * 4];          // segment max
__device__ float g_den[NN * 4];        // segment sum of exp
__device__ float g_sums[GG * HD];      // pooled sums
__device__ float g_cnt[GG];            // node counts per graph

// ---------------- helpers ----------------
__device__ __forceinline__ void atomicMaxF(float* addr, float value) {
    if (value >= 0.f) atomicMax((int*)addr, __float_as_int(value));
    else              atomicMin((unsigned int*)addr, __float_as_uint(value));
}

__global__ void fill_kernel(float* p, float v, int n) {
    int i = blockIdx.x * blockDim.x + threadIdx.x;
    if (i < n) p[i] = v;
}

// ---------------- encoder: h0 = relu(x @ W_enc + b_enc), x:[N,8], W:[8,64] ----------------
__global__ void enc_kernel(const float* __restrict__ x, const float* __restrict__ W,
                           const float* __restrict__ b, float* __restrict__ h0) {
    int idx = blockIdx.x * blockDim.x + threadIdx.x;
    if (idx >= NN * 64) return;
    int i = idx >> 6;
    int c = idx & 63;
    float acc = b[c];
#pragma unroll
    for (int k = 0; k < 8; k++) acc += x[i * 8 + k] * W[k * 64 + c];
    h0[idx] = fmaxf(acc, 0.f);
}

// ---------------- GEMM: Y[n,256] = X[n,K] @ W[K,256] + b ----------------
template <int K>
__global__ void gemm_bias_kernel(const float* __restrict__ X, const float* __restrict__ W,
                                 const float* __restrict__ b, float* __restrict__ Y, int n) {
    __shared__ float xs[32 * K];
    int row0 = blockIdx.x * 32;
    for (int idx = threadIdx.x; idx < 32 * K; idx += 256) {
        int r = idx / K;
        xs[idx] = (row0 + r < n) ? X[row0 * K + idx] : 0.f;
    }
    __syncthreads();
    int col = threadIdx.x;  // 0..255
    float acc[32];
#pragma unroll
    for (int r = 0; r < 32; r++) acc[r] = 0.f;
#pragma unroll 4
    for (int k = 0; k < K; k++) {
        float w = W[k * 256 + col];
#pragma unroll
        for (int r = 0; r < 32; r++) acc[r] += xs[r * K + k] * w;
    }
    float bias = b[col];
#pragma unroll
    for (int r = 0; r < 32; r++) {
        int row = row0 + r;
        if (row < n) Y[row * 256 + col] = acc[r] + bias;
    }
}

// ---------------- edge pass A: logit + segment max (one warp per edge) ----------------
__global__ void edge_logit_kernel(const float* __restrict__ xl, const float* __restrict__ xr,
                                  const float* __restrict__ eattr, const float* __restrict__ We,
                                  const float* __restrict__ att,
                                  const int* __restrict__ src, const int* __restrict__ dst,
                                  float* __restrict__ logit, float* __restrict__ m) {
    int e = blockIdx.x * 8 + (threadIdx.x >> 5);
    int lane = threadIdx.x & 31;
    if (e >= EE) return;
    int s = src[e], d = dst[e];
    float ea = eattr[e];
    float acc[4] = {0.f, 0.f, 0.f, 0.f};
#pragma unroll
    for (int j = 0; j < 8; j++) {
        int c = j * 32 + lane;
        float v = xl[s * 256 + c] + xr[d * 256 + c] + ea * We[c];
        v = (v > 0.f) ? v : 0.2f * v;            // leaky_relu 0.2
        acc[j >> 1] += v * att[c];               // att flat [H*C], c = h*64 + local
    }
#pragma unroll
    for (int h = 0; h < 4; h++) {
        float v = acc[h];
#pragma unroll
        for (int off = 16; off > 0; off >>= 1) v += __shfl_xor_sync(0xffffffffu, v, off);
        if (lane == 0) {
            logit[e * 4 + h] = v;
            atomicMaxF(&m[d * 4 + h], v);
        }
    }
}

// ---------------- edge pass B: exp + segment sum ----------------
__global__ void edge_exp_kernel(const int* __restrict__ dst, float* __restrict__ logit,
                                const float* __restrict__ m, float* __restrict__ den) {
    int i = blockIdx.x * blockDim.x + threadIdx.x;
    if (i >= EE * 4) return;
    int e = i >> 2, h = i & 3;
    int d = dst[e];
    float ex = __expf(logit[i] - m[d * 4 + h]);
    logit[i] = ex;
    atomicAdd(&den[d * 4 + h], ex);
}

// ---------------- edge pass C: weighted scatter (one warp per edge) ----------------
__global__ void edge_scatter_kernel(const float* __restrict__ xl, const float* __restrict__ ex,
                                    const float* __restrict__ den,
                                    const int* __restrict__ src, const int* __restrict__ dst,
                                    float* __restrict__ acc_out) {
    int e = blockIdx.x * 8 + (threadIdx.x >> 5);
    int lane = threadIdx.x & 31;
    if (e >= EE) return;
    int s = src[e], d = dst[e];
    float alpha[4];
#pragma unroll
    for (int h = 0; h < 4; h++) alpha[h] = ex[e * 4 + h] / (den[d * 4 + h] + 1e-16f);
#pragma unroll
    for (int j = 0; j < 8; j++) {
        int c = j * 32 + lane;
        atomicAdd(&acc_out[d * 256 + c], alpha[j >> 1] * xl[s * 256 + c]);
    }
}

// ---------------- h = relu(acc + bias) ----------------
__global__ void relu_bias_kernel(const float* __restrict__ acc, const float* __restrict__ bias,
                                 float* __restrict__ h) {
    int i = blockIdx.x * blockDim.x + threadIdx.x;
    if (i >= NN * 256) return;
    h[i] = fmaxf(acc[i] + bias[i & 255], 0.f);
}

// ---------------- mean pool (batch is sorted -> register accumulate + flush) ----------------
__global__ void pool_kernel(const float* __restrict__ h, const int* __restrict__ batch,
                            float* __restrict__ sums, float* __restrict__ cnt) {
    int c = threadIdx.x;  // 256 cols
    int n0 = blockIdx.x * 64;
    if (n0 >= NN) return;
    int cur = batch[n0];
    float acc = 0.f;
    float fc = 0.f;
    for (int i = 0; i < 64; i++) {
        int node = n0 + i;
        if (node >= NN) break;
        int b = batch[node];
        if (b != cur) {
            atomicAdd(&sums[cur * 256 + c], acc);
            if (c == 0) atomicAdd(&cnt[cur], fc);
            acc = 0.f; fc = 0.f; cur = b;
        }
        acc += h[node * 256 + c];
        fc += 1.f;
    }
    atomicAdd(&sums[cur * 256 + c], acc);
    if (c == 0) atomicAdd(&cnt[cur], fc);
}

// ---------------- MLP head: one block (128 thr) per graph ----------------
__global__ void head_kernel(const float* __restrict__ sums, const float* __restrict__ cnt,
                            const float* __restrict__ Wp1, const float* __restrict__ bp1,
                            const float* __restrict__ lng, const float* __restrict__ lnb,
                            const float* __restrict__ Wp2, const float* __restrict__ bp2,
                            const float* __restrict__ Wh, const float* __restrict__ bh,
                            float* __restrict__ out) {
    __shared__ float pool[256];
    __shared__ float pbuf[128];
    __shared__ float qbuf[64];
    __shared__ float redbuf[4];
    int g = blockIdx.x, t = threadIdx.x;  // 128 threads
    float cn = fmaxf(cnt[g], 1.f);
    pool[t] = sums[g * 256 + t] / cn;
    pool[t + 128] = sums[g * 256 + 128 + t] / cn;
    __syncthreads();

    float acc = bp1[t];
#pragma unroll 4
    for (int k = 0; k < 256; k++) acc += pool[k] * Wp1[k * 128 + t];

    // mean over 128
    float s = acc;
#pragma unroll
    for (int o = 16; o > 0; o >>= 1) s += __shfl_xor_sync(0xffffffffu, s, o);
    if ((t & 31) == 0) redbuf[t >> 5] = s;
    __syncthreads();
    float mu = (redbuf[0] + redbuf[1] + redbuf[2] + redbuf[3]) * (1.f / 128.f);
    __syncthreads();

    // variance (two-pass)
    float dv = (acc - mu) * (acc - mu);
#pragma unroll
    for (int o = 16; o > 0; o >>= 1) dv += __shfl_xor_sync(0xffffffffu, dv, o);
    if ((t & 31) == 0) redbuf[t >> 5] = dv;
    __syncthreads();
    float var = (redbuf[0] + redbuf[1] + redbuf[2] + redbuf[3]) * (1.f / 128.f);

    float v = (acc - mu) * rsqrtf(var + 1e-5f) * lng[t] + lnb[t];
    pbuf[t] = fmaxf(v, 0.f);
    __syncthreads();

    if (t < 64) {
        float a = bp2[t];
#pragma unroll 4
        for (int k = 0; k < 128; k++) a += pbuf[k] * Wp2[k * 64 + t];
        qbuf[t] = fmaxf(a, 0.f);
    }
    __syncthreads();

    if (t < 32) {
        float a = qbuf[t] * Wh[t] + qbuf[t + 32] * Wh[t + 32];
#pragma unroll
        for (int o = 16; o > 0; o >>= 1) a += __shfl_xor_sync(0xffffffffu, a, o);
        if (t == 0) out[g] = a + bh[0];
    }
}

// ---------------- launch ----------------
static void run_gat_layer(const float* h_in, int Kin,
                          const float* Wl, const float* bl,
                          const float* Wr, const float* br,
                          const float* We, const float* att, const float* bias,
                          const float* eattr, const int* src, const int* dst,
                          float* xl, float* xr, float* accb, float* h_out,
                          float* logit, float* m, float* den) {
    // transforms
    if (Kin == 64) {
        gemm_bias_kernel<64><<<(NN + 31) / 32, 256>>>(h_in, Wl, bl, xl, NN);
        gemm_bias_kernel<64><<<(NN + 31) / 32, 256>>>(h_in, Wr, br, xr, NN);
    } else {
        gemm_bias_kernel<256><<<(NN + 31) / 32, 256>>>(h_in, Wl, bl, xl, NN);
        gemm_bias_kernel<256><<<(NN + 31) / 32, 256>>>(h_in, Wr, br, xr, NN);
    }
    // init scratch
    fill_kernel<<<(NN * 4 + 255) / 256, 256>>>(m, -INFINITY, NN * 4);
    fill_kernel<<<(NN * 4 + 255) / 256, 256>>>(den, 0.f, NN * 4);
    fill_kernel<<<(NN * 256 + 255) / 256, 256>>>(accb, 0.f, NN * 256);
    // edge passes
    edge_logit_kernel<<<(EE + 7) / 8, 256>>>(xl, xr, eattr, We, att, src, dst, logit, m);
    edge_exp_kernel<<<(EE * 4 + 255) / 256, 256>>>(dst, logit, m, den);
    edge_scatter_kernel<<<(EE + 7) / 8, 256>>>(xl, logit, den, src, dst, accb);
    relu_bias_kernel<<<(NN * 256 + 255) / 256, 256>>>(accb, bias, h_out);
}

extern "C" void kernel_launch(void* const* d_in, const int* in_sizes, int n_in,
                              void* d_out, int out_size) {
    const float* x       = (const float*)d_in[0];
    const float* eattr   = (const float*)d_in[1];
    const int*   src     = (const int*)d_in[2];
    const int*   dst     = (const int*)d_in[3];
    const int*   batch   = (const int*)d_in[4];
    const float* W_enc   = (const float*)d_in[5];
    const float* b_enc   = (const float*)d_in[6];
    const float* g1_Wl   = (const float*)d_in[7];
    const float* g1_bl   = (const float*)d_in[8];
    const float* g1_Wr   = (const float*)d_in[9];
    const float* g1_br   = (const float*)d_in[10];
    const float* g1_We   = (const float*)d_in[11];
    const float* g1_att  = (const float*)d_in[12];
    const float* g1_bias = (const float*)d_in[13];
    const float* g2_Wl   = (const float*)d_in[14];
    const float* g2_bl   = (const float*)d_in[15];
    const float* g2_Wr   = (const float*)d_in[16];
    const float* g2_br   = (const float*)d_in[17];
    const float* g2_We   = (const float*)d_in[18];
    const float* g2_att  = (const float*)d_in[19];
    const float* g2_bias = (const float*)d_in[20];
    const float* W_p1    = (const float*)d_in[21];
    const float* b_p1    = (const float*)d_in[22];
    const float* ln_g    = (const float*)d_in[23];
    const float* ln_b    = (const float*)d_in[24];
    const float* W_p2    = (const float*)d_in[25];
    const float* b_p2    = (const float*)d_in[26];
    const float* W_head  = (const float*)d_in[27];
    const float* b_head  = (const float*)d_in[28];
    float* out = (float*)d_out;

    float *h0, *xl, *xr, *accb, *h1, *logit, *m, *den, *sums, *cnt;
    cudaGetSymbolAddress((void**)&h0,    g_h0);
    cudaGetSymbolAddress((void**)&xl,    g_xl);
    cudaGetSymbolAddress((void**)&xr,    g_xr);
    cudaGetSymbolAddress((void**)&accb,  g_acc);
    cudaGetSymbolAddress((void**)&h1,    g_h1);
    cudaGetSymbolAddress((void**)&logit, g_logit);
    cudaGetSymbolAddress((void**)&m,     g_m);
    cudaGetSymbolAddress((void**)&den,   g_den);
    cudaGetSymbolAddress((void**)&sums,  g_sums);
    cudaGetSymbolAddress((void**)&cnt,   g_cnt);

    // encoder
    enc_kernel<<<(NN * 64 + 255) / 256, 256>>>(x, W_enc, b_enc, h0);

    // GAT layer 1 (in=64) -> h1
    run_gat_layer(h0, 64, g1_Wl, g1_bl, g1_Wr, g1_br, g1_We, g1_att, g1_bias,
                  eattr, src, dst, xl, xr, accb, h1, logit, m, den);

    // GAT layer 2 (in=256) -> h1 (overwrites; xl consumed before relu_bias writes)
    run_gat_layer(h1, 256, g2_Wl, g2_bl, g2_Wr, g2_br, g2_We, g2_att, g2_bias,
                  eattr, src, dst, xl, xr, accb, h1, logit, m, den);

    // pool
    fill_kernel<<<(GG * 256 + 255) / 256, 256>>>(sums, 0.f, GG * 256);
    fill_kernel<<<1, 64>>>(cnt, 0.f, GG);
    pool_kernel<<<(NN + 63) / 64, 256>>>(h1, batch, sums, cnt);

    // head
    head_kernel<<<GG, 128>>>(sums, cnt, W_p1, b_p1, ln_g, ln_b, W_p2, b_p2,
                             W_head, b_head, out);
}

// round 3
// speedup vs baseline: 1.5943x; 1.5943x over previous
#include <cuda_runtime.h>
#include <cuda_bf16.h>
#include <math.h>
#include <cstdint>

#define NN 100000
#define EE 400000
#define GG 64

// ---------------- scratch (device globals; no allocation allowed) ----------------
__device__ float g_h0[NN * 64];        // encoder output
__device__ float g_xl[NN * 256];       // source-side transform
__device__ float g_xr[NN * 256];       // target-side transform
__device__ float g_acc[NN * 256];      // attention-weighted scatter accumulator
__device__ float g_h1[NN * 256];       // layer output
__device__ float g_logit[EE * 4];      // per-edge per-head logit, then exp
__device__ float g_m[NN * 4];          // segment max
__device__ float g_den[NN * 4];        // segment sum of exp
__device__ float g_sums[GG * 256];     // pooled sums
__device__ float g_cnt[GG];            // node counts per graph
__device__ float g_wt[512 * 256];      // fused transposed weights [512 n-rows, K] K-major

// ---------------- helpers ----------------
__device__ __forceinline__ void atomicMaxF(float* addr, float value) {
    if (value >= 0.f) atomicMax((int*)addr, __float_as_int(value));
    else              atomicMin((unsigned int*)addr, __float_as_uint(value));
}

__device__ __forceinline__ uint32_t cvt_tf32(float x) {
    uint32_t r;
    asm("cvt.rna.tf32.f32 %0, %1;" : "=r"(r) : "f"(x));
    return r;
}

__device__ __forceinline__ void mma_tf32_16x8x8(float* d, const uint32_t* a, const uint32_t* b) {
    asm volatile(
        "mma.sync.aligned.m16n8k8.row.col.f32.tf32.tf32.f32 "
        "{%0,%1,%2,%3}, {%4,%5,%6,%7}, {%8,%9}, {%0,%1,%2,%3};"
        : "+f"(d[0]), "+f"(d[1]), "+f"(d[2]), "+f"(d[3])
        : "r"(a[0]), "r"(a[1]), "r"(a[2]), "r"(a[3]), "r"(b[0]), "r"(b[1]));
}

__global__ void fill_kernel(float* p, float v, int n) {
    int i = blockIdx.x * blockDim.x + threadIdx.x;
    if (i < n) p[i] = v;
}

// ---------------- tf32 MMA GEMM: [xl|xr] = X[n,K] @ WT[512,K]^T + bias ----------------
// Grid (Mtiles, 4). CTA tile 128x128. 8 warps: 2(M) x 4(N), warp tile 64x32.
// K streamed in 32-float chunks, double-buffered smem with 36-float row pitch
// (bank = (4q + k) mod 32 -> conflict-free fragment loads).
#define ROWPITCH 36
#define STAGEF (128 * ROWPITCH)          // floats per (A or B) stage

template <int K>
__global__ void __launch_bounds__(256, 1)
mma_lr_kernel(const float* __restrict__ X, const float* __restrict__ WT,
              const float* __restrict__ bl, const float* __restrict__ br,
              float* __restrict__ xl, float* __restrict__ xr, int n) {
    extern __shared__ float smf[];       // [2 stages][A(128x36) then B(128x36)]
    constexpr int NC = K / 32;

    int tid = threadIdx.x;
    int wid = tid >> 5, lane = tid & 31;
    int wm = wid & 1, wn = wid >> 1;     // warp coords: 2(M) x 4(N)
    int tg = lane >> 2, tig = lane & 3;  // thread-group row / in-group col
    int row0 = blockIdx.x * 128;
    int nbase = blockIdx.y * 128;        // fused-col base (0..511)

    float d[4][4][4];                    // [mt][nt][c-frag]
#pragma unroll
    for (int i = 0; i < 4; i++)
#pragma unroll
        for (int j = 0; j < 4; j++)
#pragma unroll
            for (int q = 0; q < 4; q++) d[i][j][q] = 0.f;

    // per-thread LDG buffers: 4 float4 for A, 4 float4 for B per chunk
    float4 abuf[4], bbuf[4];

    auto ldg_chunk = [&](int c) {
#pragma unroll
        for (int j = 0; j < 4; j++) {
            int i = tid + j * 256;       // 0..1023 float4 slots
            int r = i >> 3, q = i & 7;   // 8 float4 per 32-float row
            int row = row0 + r;
            abuf[j] = (row < n) ? *(const float4*)&X[row * K + c * 32 + q * 4]
                                : make_float4(0.f, 0.f, 0.f, 0.f);
            bbuf[j] = *(const float4*)&WT[(nbase + r) * K + c * 32 + q * 4];
        }
    };
    auto sts_chunk = [&](int s) {
        float* As = smf + s * (2 * STAGEF);
        float* Bs = As + STAGEF;
#pragma unroll
        for (int j = 0; j < 4; j++) {
            int i = tid + j * 256;
            int r = i >> 3, q = i & 7;
            uint32_t* pa = (uint32_t*)&As[r * ROWPITCH + q * 4];
            pa[0] = cvt_tf32(abuf[j].x); pa[1] = cvt_tf32(abuf[j].y);
            pa[2] = cvt_tf32(abuf[j].z); pa[3] = cvt_tf32(abuf[j].w);
            uint32_t* pb = (uint32_t*)&Bs[r * ROWPITCH + q * 4];
            pb[0] = cvt_tf32(bbuf[j].x); pb[1] = cvt_tf32(bbuf[j].y);
            pb[2] = cvt_tf32(bbuf[j].z); pb[3] = cvt_tf32(bbuf[j].w);
        }
    };

    ldg_chunk(0);
    sts_chunk(0);
    __syncthreads();

    for (int c = 0; c < NC; c++) {
        int s = c & 1;
        if (c + 1 < NC) ldg_chunk(c + 1);

        const uint32_t* As = (const uint32_t*)(smf + s * (2 * STAGEF));
        const uint32_t* Bs = As + STAGEF;
#pragma unroll
        for (int ks = 0; ks < 4; ks++) {
            uint32_t a[4][4], b[4][2];
#pragma unroll
            for (int mt = 0; mt < 4; mt++) {
                const uint32_t* p = As + (wm * 64 + mt * 16 + tg) * ROWPITCH + ks * 8 + tig;
                a[mt][0] = p[0];
                a[mt][1] = p[8 * ROWPITCH];
                a[mt][2] = p[4];
                a[mt][3] = p[8 * ROWPITCH + 4];
            }
#pragma unroll
            for (int nt = 0; nt < 4; nt++) {
                const uint32_t* p = Bs + (wn * 32 + nt * 8 + tg) * ROWPITCH + ks * 8 + tig;
                b[nt][0] = p[0];
                b[nt][1] = p[4];
            }
#pragma unroll
            for (int mt = 0; mt < 4; mt++)
#pragma unroll
                for (int nt = 0; nt < 4; nt++)
                    mma_tf32_16x8x8(d[mt][nt], a[mt], b[nt]);
        }

        if (c + 1 < NC) {
            __syncthreads();
            sts_chunk((c + 1) & 1);
            __syncthreads();
        }
    }

    // epilogue: blockIdx.y 0,1 -> xl cols 0..255 ; 2,3 -> xr
    float* Y = (blockIdx.y < 2) ? xl : xr;
    const float* bias = (blockIdx.y < 2) ? bl : br;
    int colb = (blockIdx.y & 1) * 128;
#pragma unroll
    for (int mt = 0; mt < 4; mt++) {
        int r0 = row0 + wm * 64 + mt * 16 + tg;
#pragma unroll
        for (int nt = 0; nt < 4; nt++) {
            int col = colb + wn * 32 + nt * 8 + 2 * tig;
            float2 bv = *(const float2*)&bias[col];
            if (r0 < n)
                *(float2*)&Y[r0 * 256 + col] =
                    make_float2(d[mt][nt][0] + bv.x, d[mt][nt][1] + bv.y);
            if (r0 + 8 < n)
                *(float2*)&Y[(r0 + 8) * 256 + col] =
                    make_float2(d[mt][nt][2] + bv.x, d[mt][nt][3] + bv.y);
        }
    }
}

// build WT[512,K] K-major from Wl/Wr [K,256]
__global__ void build_wt_kernel(const float* __restrict__ Wl, const float* __restrict__ Wr,
                                float* __restrict__ WT, int K) {
    int idx = blockIdx.x * blockDim.x + threadIdx.x;
    if (idx >= 512 * K) return;
    int nrow = idx / K, k = idx - nrow * K;
    WT[idx] = (nrow < 256) ? Wl[k * 256 + nrow] : Wr[k * 256 + (nrow - 256)];
}

// ---------------- encoder: h0 = relu(x @ W_enc + b_enc) ----------------
__global__ void enc_kernel(const float* __restrict__ x, const float* __restrict__ W,
                           const float* __restrict__ b, float* __restrict__ h0) {
    int idx = blockIdx.x * blockDim.x + threadIdx.x;
    if (idx >= NN * 64) return;
    int i = idx >> 6;
    int c = idx & 63;
    float acc = b[c];
#pragma unroll
    for (int k = 0; k < 8; k++) acc += x[i * 8 + k] * W[k * 64 + c];
    h0[idx] = fmaxf(acc, 0.f);
}

// ---------------- edge pass A: logit + segment max (one warp per edge) ----------------
__global__ void edge_logit_kernel(const float* __restrict__ xl, const float* __restrict__ xr,
                                  const float* __restrict__ eattr, const float* __restrict__ We,
                                  const float* __restrict__ att,
                                  const int* __restrict__ src, const int* __restrict__ dst,
                                  float* __restrict__ logit, float* __restrict__ m) {
    int e = blockIdx.x * 8 + (threadIdx.x >> 5);
    int lane = threadIdx.x & 31;
    if (e >= EE) return;
    int s = src[e], d = dst[e];
    float ea = eattr[e];
    float acc[4] = {0.f, 0.f, 0.f, 0.f};
#pragma unroll
    for (int j = 0; j < 8; j++) {
        int c = j * 32 + lane;
        float v = xl[s * 256 + c] + xr[d * 256 + c] + ea * We[c];
        v = (v > 0.f) ? v : 0.2f * v;
        acc[j >> 1] += v * att[c];
    }
#pragma unroll
    for (int h = 0; h < 4; h++) {
        float v = acc[h];
#pragma unroll
        for (int off = 16; off > 0; off >>= 1) v += __shfl_xor_sync(0xffffffffu, v, off);
        if (lane == 0) {
            logit[e * 4 + h] = v;
            atomicMaxF(&m[d * 4 + h], v);
        }
    }
}

// ---------------- edge pass B: exp + segment sum ----------------
__global__ void edge_exp_kernel(const int* __restrict__ dst, float* __restrict__ logit,
                                const float* __restrict__ m, float* __restrict__ den) {
    int i = blockIdx.x * blockDim.x + threadIdx.x;
    if (i >= EE * 4) return;
    int e = i >> 2, h = i & 3;
    int d = dst[e];
    float ex = __expf(logit[i] - m[d * 4 + h]);
    logit[i] = ex;
    atomicAdd(&den[d * 4 + h], ex);
}

// ---------------- edge pass C: weighted scatter (vector red) ----------------
__global__ void edge_scatter_kernel(const float* __restrict__ xl, const float* __restrict__ ex,
                                    const float* __restrict__ den,
                                    const int* __restrict__ src, const int* __restrict__ dst,
                                    float* __restrict__ acc_out) {
    int e = blockIdx.x * 8 + (threadIdx.x >> 5);
    int lane = threadIdx.x & 31;
    if (e >= EE) return;
    int s = src[e], d = dst[e];
    float alpha[4];
#pragma unroll
    for (int h = 0; h < 4; h++) alpha[h] = ex[e * 4 + h] / (den[d * 4 + h] + 1e-16f);
#pragma unroll
    for (int j = 0; j < 2; j++) {
        int cbase = j * 128 + lane * 4;
        float4 v = *(const float4*)&xl[s * 256 + cbase];
        float a = alpha[cbase >> 6];
        float* p = &acc_out[d * 256 + cbase];
        asm volatile("red.global.add.v4.f32 [%0], {%1, %2, %3, %4};"
                     :: "l"(p), "f"(v.x * a), "f"(v.y * a), "f"(v.z * a), "f"(v.w * a)
                     : "memory");
    }
}

// ---------------- h = relu(acc + bias) ----------------
__global__ void relu_bias_kernel(const float* __restrict__ acc, const float* __restrict__ bias,
                                 float* __restrict__ h) {
    int i = blockIdx.x * blockDim.x + threadIdx.x;
    if (i >= NN * 256) return;
    h[i] = fmaxf(acc[i] + bias[i & 255], 0.f);
}

// ---------------- mean pool (batch sorted -> register accumulate + flush) ----------------
__global__ void pool_kernel(const float* __restrict__ h, const int* __restrict__ batch,
                            float* __restrict__ sums, float* __restrict__ cnt) {
    int c = threadIdx.x;
    int n0 = blockIdx.x * 64;
    if (n0 >= NN) return;
    int cur = batch[n0];
    float acc = 0.f, fc = 0.f;
    for (int i = 0; i < 64; i++) {
        int node = n0 + i;
        if (node >= NN) break;
        int b = batch[node];
        if (b != cur) {
            atomicAdd(&sums[cur * 256 + c], acc);
            if (c == 0) atomicAdd(&cnt[cur], fc);
            acc = 0.f; fc = 0.f; cur = b;
        }
        acc += h[node * 256 + c];
        fc += 1.f;
    }
    atomicAdd(&sums[cur * 256 + c], acc);
    if (c == 0) atomicAdd(&cnt[cur], fc);
}

// ---------------- MLP head: one block (128 thr) per graph ----------------
__global__ void head_kernel(const float* __restrict__ sums, const float* __restrict__ cnt,
                            const float* __restrict__ Wp1, const float* __restrict__ bp1,
                            const float* __restrict__ lng, const float* __restrict__ lnb,
                            const float* __restrict__ Wp2, const float* __restrict__ bp2,
                            const float* __restrict__ Wh, const float* __restrict__ bh,
                            float* __restrict__ out) {
    __shared__ float pool[256];
    __shared__ float pbuf[128];
    __shared__ float qbuf[64];
    __shared__ float redbuf[4];
    int g = blockIdx.x, t = threadIdx.x;
    float cn = fmaxf(cnt[g], 1.f);
    pool[t] = sums[g * 256 + t] / cn;
    pool[t + 128] = sums[g * 256 + 128 + t] / cn;
    __syncthreads();

    float acc = bp1[t];
#pragma unroll 4
    for (int k = 0; k < 256; k++) acc += pool[k] * Wp1[k * 128 + t];

    float s = acc;
#pragma unroll
    for (int o = 16; o > 0; o >>= 1) s += __shfl_xor_sync(0xffffffffu, s, o);
    if ((t & 31) == 0) redbuf[t >> 5] = s;
    __syncthreads();
    float mu = (redbuf[0] + redbuf[1] + redbuf[2] + redbuf[3]) * (1.f / 128.f);
    __syncthreads();

    float dv = (acc - mu) * (acc - mu);
#pragma unroll
    for (int o = 16; o > 0; o >>= 1) dv += __shfl_xor_sync(0xffffffffu, dv, o);
    if ((t & 31) == 0) redbuf[t >> 5] = dv;
    __syncthreads();
    float var = (redbuf[0] + redbuf[1] + redbuf[2] + redbuf[3]) * (1.f / 128.f);

    float v = (acc - mu) * rsqrtf(var + 1e-5f) * lng[t] + lnb[t];
    pbuf[t] = fmaxf(v, 0.f);
    __syncthreads();

    if (t < 64) {
        float a = bp2[t];
#pragma unroll 4
        for (int k = 0; k < 128; k++) a += pbuf[k] * Wp2[k * 64 + t];
        qbuf[t] = fmaxf(a, 0.f);
    }
    __syncthreads();

    if (t < 32) {
        float a = qbuf[t] * Wh[t] + qbuf[t + 32] * Wh[t + 32];
#pragma unroll
        for (int o = 16; o > 0; o >>= 1) a += __shfl_xor_sync(0xffffffffu, a, o);
        if (t == 0) out[g] = a + bh[0];
    }
}

// ---------------- launch ----------------
static const int MMA_SMEM = 2 * 2 * STAGEF * 4;   // 2 stages x (A+B) x 4608 floats = 73728 B

static void run_edges(const float* xl, const float* xr,
                      const float* We, const float* att, const float* bias,
                      const float* eattr, const int* src, const int* dst,
                      float* accb, float* h_out, float* logit, float* m, float* den) {
    fill_kernel<<<(NN * 4 + 255) / 256, 256>>>(m, -INFINITY, NN * 4);
    fill_kernel<<<(NN * 4 + 255) / 256, 256>>>(den, 0.f, NN * 4);
    fill_kernel<<<(NN * 256 + 255) / 256, 256>>>(accb, 0.f, NN * 256);
    edge_logit_kernel<<<(EE + 7) / 8, 256>>>(xl, xr, eattr, We, att, src, dst, logit, m);
    edge_exp_kernel<<<(EE * 4 + 255) / 256, 256>>>(dst, logit, m, den);
    edge_scatter_kernel<<<(EE + 7) / 8, 256>>>(xl, logit, den, src, dst, accb);
    relu_bias_kernel<<<(NN * 256 + 255) / 256, 256>>>(accb, bias, h_out);
}

extern "C" void kernel_launch(void* const* d_in, const int* in_sizes, int n_in,
                              void* d_out, int out_size) {
    const float* x       = (const float*)d_in[0];
    const float* eattr   = (const float*)d_in[1];
    const int*   src     = (const int*)d_in[2];
    const int*   dst     = (const int*)d_in[3];
    const int*   batch   = (const int*)d_in[4];
    const float* W_enc   = (const float*)d_in[5];
    const float* b_enc   = (const float*)d_in[6];
    const float* g1_Wl   = (const float*)d_in[7];
    const float* g1_bl   = (const float*)d_in[8];
    const float* g1_Wr   = (const float*)d_in[9];
    const float* g1_br   = (const float*)d_in[10];
    const float* g1_We   = (const float*)d_in[11];
    const float* g1_att  = (const float*)d_in[12];
    const float* g1_bias = (const float*)d_in[13];
    const float* g2_Wl   = (const float*)d_in[14];
    const float* g2_bl   = (const float*)d_in[15];
    const float* g2_Wr   = (const float*)d_in[16];
    const float* g2_br   = (const float*)d_in[17];
    const float* g2_We   = (const float*)d_in[18];
    const float* g2_att  = (const float*)d_in[19];
    const float* g2_bias = (const float*)d_in[20];
    const float* W_p1    = (const float*)d_in[21];
    const float* b_p1    = (const float*)d_in[22];
    const float* ln_g    = (const float*)d_in[23];
    const float* ln_b    = (const float*)d_in[24];
    const float* W_p2    = (const float*)d_in[25];
    const float* b_p2    = (const float*)d_in[26];
    const float* W_head  = (const float*)d_in[27];
    const float* b_head  = (const float*)d_in[28];
    float* out = (float*)d_out;

    float *h0, *xl, *xr, *accb, *h1, *logit, *m, *den, *sums, *cnt, *wt;
    cudaGetSymbolAddress((void**)&h0,    g_h0);
    cudaGetSymbolAddress((void**)&xl,    g_xl);
    cudaGetSymbolAddress((void**)&xr,    g_xr);
    cudaGetSymbolAddress((void**)&accb,  g_acc);
    cudaGetSymbolAddress((void**)&h1,    g_h1);
    cudaGetSymbolAddress((void**)&logit, g_logit);
    cudaGetSymbolAddress((void**)&m,     g_m);
    cudaGetSymbolAddress((void**)&den,   g_den);
    cudaGetSymbolAddress((void**)&sums,  g_sums);
    cudaGetSymbolAddress((void**)&cnt,   g_cnt);
    cudaGetSymbolAddress((void**)&wt,    g_wt);

    cudaFuncSetAttribute(mma_lr_kernel<64>,  cudaFuncAttributeMaxDynamicSharedMemorySize, MMA_SMEM);
    cudaFuncSetAttribute(mma_lr_kernel<256>, cudaFuncAttributeMaxDynamicSharedMemorySize, MMA_SMEM);

    const int MT = (NN + 127) / 128;
    dim3 gemm_grid(MT, 4);

    // encoder
    enc_kernel<<<(NN * 64 + 255) / 256, 256>>>(x, W_enc, b_enc, h0);

    // GAT layer 1 (K=64)
    build_wt_kernel<<<(512 * 64 + 255) / 256, 256>>>(g1_Wl, g1_Wr, wt, 64);
    mma_lr_kernel<64><<<gemm_grid, 256, MMA_SMEM>>>(h0, wt, g1_bl, g1_br, xl, xr, NN);
    run_edges(xl, xr, g1_We, g1_att, g1_bias, eattr, src, dst, accb, h1, logit, m, den);

    // GAT layer 2 (K=256)
    build_wt_kernel<<<(512 * 256 + 255) / 256, 256>>>(g2_Wl, g2_Wr, wt, 256);
    mma_lr_kernel<256><<<gemm_grid, 256, MMA_SMEM>>>(h1, wt, g2_bl, g2_br, xl, xr, NN);
    run_edges(xl, xr, g2_We, g2_att, g2_bias, eattr, src, dst, accb, h1, logit, m, den);

    // pool + head
    fill_kernel<<<(GG * 256 + 255) / 256, 256>>>(sums, 0.f, GG * 256);
    fill_kernel<<<1, 64>>>(cnt, 0.f, GG);
    pool_kernel<<<(NN + 63) / 64, 256>>>(h1, batch, sums, cnt);
    head_kernel<<<GG, 128>>>(sums, cnt, W_p1, b_p1, ln_g, ln_b, W_p2, b_p2, W_head, b_head, out);
}

// round 4
// speedup vs baseline: 2.5043x; 1.5708x over previous
#include <cuda_runtime.h>
#include <cuda_bf16.h>
#include <math.h>
#include <cstdint>

#define NN 100000
#define EE 400000
#define GG 64

// ---------------- scratch (device globals; no allocation allowed) ----------------
__device__ float g_h0[NN * 64];        // encoder output
__device__ float g_xl[NN * 256];       // source-side transform
__device__ float g_xr[NN * 256];       // target-side transform
__device__ float g_h1[NN * 256];       // layer output
__device__ float g_sums[GG * 256];     // pooled sums
__device__ float g_cnt[GG];            // node counts per graph
__device__ float g_wt[512 * 256];      // fused transposed weights [512 n-rows, K] K-major
// CSR over dst (built once per launch; dst shared by both layers)
__device__ int g_rowptr[NN + 1];
__device__ int g_cursor[NN];           // also used as histogram counts
__device__ int g_coleid[EE];
__device__ int g_bsums[128];

// ---------------- small utils ----------------
__global__ void fill_kernel(float* p, float v, int n) {
    int i = blockIdx.x * blockDim.x + threadIdx.x;
    if (i < n) p[i] = v;
}
__global__ void fill_int_kernel(int* p, int v, int n) {
    int i = blockIdx.x * blockDim.x + threadIdx.x;
    if (i < n) p[i] = v;
}

__device__ __forceinline__ uint32_t cvt_tf32(float x) {
    uint32_t r;
    asm("cvt.rna.tf32.f32 %0, %1;" : "=r"(r) : "f"(x));
    return r;
}
__device__ __forceinline__ void mma_tf32_16x8x8(float* d, const uint32_t* a, const uint32_t* b) {
    asm volatile(
        "mma.sync.aligned.m16n8k8.row.col.f32.tf32.tf32.f32 "
        "{%0,%1,%2,%3}, {%4,%5,%6,%7}, {%8,%9}, {%0,%1,%2,%3};"
        : "+f"(d[0]), "+f"(d[1]), "+f"(d[2]), "+f"(d[3])
        : "r"(a[0]), "r"(a[1]), "r"(a[2]), "r"(a[3]), "r"(b[0]), "r"(b[1]));
}

// ---------------- CSR build over dst ----------------
__global__ void hist_kernel(const int* __restrict__ dst, int* __restrict__ cnts) {
    int e = blockIdx.x * blockDim.x + threadIdx.x;
    if (e < EE) atomicAdd(&cnts[dst[e]], 1);
}
// block-local inclusive scan of 1024 counts -> rowptr[i+1] (no offset), block sums
__global__ void scan1_kernel(const int* __restrict__ cnts, int* __restrict__ rowptr,
                             int* __restrict__ bsums) {
    __shared__ int buf[2][1024];
    int b = blockIdx.x, t = threadIdx.x;
    int i = b * 1024 + t;
    buf[0][t] = (i < NN) ? cnts[i] : 0;
    __syncthreads();
    int cur = 0;
#pragma unroll
    for (int off = 1; off < 1024; off <<= 1) {
        int x = buf[cur][t];
        if (t >= off) x += buf[cur][t - off];
        buf[cur ^ 1][t] = x;
        cur ^= 1;
        __syncthreads();
    }
    int inc = buf[cur][t];
    if (i < NN) rowptr[i + 1] = inc;
    if (t == 1023) bsums[b] = inc;
}
// exclusive scan of block sums (nb <= 128), single block of 128
__global__ void scan2_kernel(int* __restrict__ bsums, int nb) {
    __shared__ int buf[2][128];
    int t = threadIdx.x;
    int v = (t < nb) ? bsums[t] : 0;
    buf[0][t] = v;
    __syncthreads();
    int cur = 0;
#pragma unroll
    for (int off = 1; off < 128; off <<= 1) {
        int x = buf[cur][t];
        if (t >= off) x += buf[cur][t - off];
        buf[cur ^ 1][t] = x;
        cur ^= 1;
        __syncthreads();
    }
    if (t < nb) bsums[t] = buf[cur][t] - v;   // exclusive
}
__global__ void scan3_kernel(int* __restrict__ rowptr, const int* __restrict__ bsums,
                             int* __restrict__ cursor) {
    int b = blockIdx.x, t = threadIdx.x;
    int i = b * 1024 + t;
    if (i < NN) {
        int rp1 = rowptr[i + 1] + bsums[b];
        rowptr[i + 1] = rp1;
    }
    if (i == 0) rowptr[0] = 0;
}
__global__ void cursor_kernel(const int* __restrict__ rowptr, int* __restrict__ cursor) {
    int i = blockIdx.x * blockDim.x + threadIdx.x;
    if (i < NN) cursor[i] = rowptr[i];
}
__global__ void fillcol_kernel(const int* __restrict__ dst, int* __restrict__ cursor,
                               int* __restrict__ coleid) {
    int e = blockIdx.x * blockDim.x + threadIdx.x;
    if (e >= EE) return;
    int pos = atomicAdd(&cursor[dst[e]], 1);
    coleid[pos] = e;
}

// ---------------- tf32 MMA GEMM: [xl|xr] = X[n,K] @ WT[512,K]^T + bias ----------------
#define ROWPITCH 36
#define STAGEF (128 * ROWPITCH)

template <int K>
__global__ void __launch_bounds__(256, 1)
mma_lr_kernel(const float* __restrict__ X, const float* __restrict__ WT,
              const float* __restrict__ bl, const float* __restrict__ br,
              float* __restrict__ xl, float* __restrict__ xr, int n) {
    extern __shared__ float smf[];
    constexpr int NC = K / 32;

    int tid = threadIdx.x;
    int wid = tid >> 5, lane = tid & 31;
    int wm = wid & 1, wn = wid >> 1;
    int tg = lane >> 2, tig = lane & 3;
    int row0 = blockIdx.x * 128;
    int nbase = blockIdx.y * 128;

    float d[4][4][4];
#pragma unroll
    for (int i = 0; i < 4; i++)
#pragma unroll
        for (int j = 0; j < 4; j++)
#pragma unroll
            for (int q = 0; q < 4; q++) d[i][j][q] = 0.f;

    float4 abuf[4], bbuf[4];
    auto ldg_chunk = [&](int c) {
#pragma unroll
        for (int j = 0; j < 4; j++) {
            int i = tid + j * 256;
            int r = i >> 3, q = i & 7;
            int row = row0 + r;
            abuf[j] = (row < n) ? *(const float4*)&X[row * K + c * 32 + q * 4]
                                : make_float4(0.f, 0.f, 0.f, 0.f);
            bbuf[j] = *(const float4*)&WT[(nbase + r) * K + c * 32 + q * 4];
        }
    };
    auto sts_chunk = [&](int s) {
        float* As = smf + s * (2 * STAGEF);
        float* Bs = As + STAGEF;
#pragma unroll
        for (int j = 0; j < 4; j++) {
            int i = tid + j * 256;
            int r = i >> 3, q = i & 7;
            uint32_t* pa = (uint32_t*)&As[r * ROWPITCH + q * 4];
            pa[0] = cvt_tf32(abuf[j].x); pa[1] = cvt_tf32(abuf[j].y);
            pa[2] = cvt_tf32(abuf[j].z); pa[3] = cvt_tf32(abuf[j].w);
            uint32_t* pb = (uint32_t*)&Bs[r * ROWPITCH + q * 4];
            pb[0] = cvt_tf32(bbuf[j].x); pb[1] = cvt_tf32(bbuf[j].y);
            pb[2] = cvt_tf32(bbuf[j].z); pb[3] = cvt_tf32(bbuf[j].w);
        }
    };

    ldg_chunk(0);
    sts_chunk(0);
    __syncthreads();

    for (int c = 0; c < NC; c++) {
        int s = c & 1;
        if (c + 1 < NC) ldg_chunk(c + 1);

        const uint32_t* As = (const uint32_t*)(smf + s * (2 * STAGEF));
        const uint32_t* Bs = As + STAGEF;
#pragma unroll
        for (int ks = 0; ks < 4; ks++) {
            uint32_t a[4][4], b[4][2];
#pragma unroll
            for (int mt = 0; mt < 4; mt++) {
                const uint32_t* p = As + (wm * 64 + mt * 16 + tg) * ROWPITCH + ks * 8 + tig;
                a[mt][0] = p[0];
                a[mt][1] = p[8 * ROWPITCH];
                a[mt][2] = p[4];
                a[mt][3] = p[8 * ROWPITCH + 4];
            }
#pragma unroll
            for (int nt = 0; nt < 4; nt++) {
                const uint32_t* p = Bs + (wn * 32 + nt * 8 + tg) * ROWPITCH + ks * 8 + tig;
                b[nt][0] = p[0];
                b[nt][1] = p[4];
            }
#pragma unroll
            for (int mt = 0; mt < 4; mt++)
#pragma unroll
                for (int nt = 0; nt < 4; nt++)
                    mma_tf32_16x8x8(d[mt][nt], a[mt], b[nt]);
        }

        if (c + 1 < NC) {
            __syncthreads();
            sts_chunk((c + 1) & 1);
            __syncthreads();
        }
    }

    float* Y = (blockIdx.y < 2) ? xl : xr;
    const float* bias = (blockIdx.y < 2) ? bl : br;
    int colb = (blockIdx.y & 1) * 128;
#pragma unroll
    for (int mt = 0; mt < 4; mt++) {
        int r0 = row0 + wm * 64 + mt * 16 + tg;
#pragma unroll
        for (int nt = 0; nt < 4; nt++) {
            int col = colb + wn * 32 + nt * 8 + 2 * tig;
            float2 bv = *(const float2*)&bias[col];
            if (r0 < n)
                *(float2*)&Y[r0 * 256 + col] =
                    make_float2(d[mt][nt][0] + bv.x, d[mt][nt][1] + bv.y);
            if (r0 + 8 < n)
                *(float2*)&Y[(r0 + 8) * 256 + col] =
                    make_float2(d[mt][nt][2] + bv.x, d[mt][nt][3] + bv.y);
        }
    }
}

__global__ void build_wt_kernel(const float* __restrict__ Wl, const float* __restrict__ Wr,
                                float* __restrict__ WT, int K) {
    int idx = blockIdx.x * blockDim.x + threadIdx.x;
    if (idx >= 512 * K) return;
    int nrow = idx / K, k = idx - nrow * K;
    WT[idx] = (nrow < 256) ? Wl[k * 256 + nrow] : Wr[k * 256 + (nrow - 256)];
}

// ---------------- encoder ----------------
__global__ void enc_kernel(const float* __restrict__ x, const float* __restrict__ W,
                           const float* __restrict__ b, float* __restrict__ h0) {
    int idx = blockIdx.x * blockDim.x + threadIdx.x;
    if (idx >= NN * 64) return;
    int i = idx >> 6;
    int c = idx & 63;
    float acc = b[c];
#pragma unroll
    for (int k = 0; k < 8; k++) acc += x[i * 8 + k] * W[k * 64 + c];
    h0[idx] = fmaxf(acc, 0.f);
}

// ---------------- fused GAT aggregation: one warp per dst node, online softmax ----------------
// lane owns channels c0 = lane*8 .. +7 (all within head lane>>3; 8 lanes per head).
__global__ void __launch_bounds__(256)
edge_fused_kernel(const float* __restrict__ xl, const float* __restrict__ xr,
                  const float* __restrict__ eattr, const float* __restrict__ We,
                  const float* __restrict__ att,
                  const int* __restrict__ src,
                  const int* __restrict__ rowptr, const int* __restrict__ coleid,
                  const float* __restrict__ bias, float* __restrict__ h_out) {
    int d = blockIdx.x * 8 + (threadIdx.x >> 5);
    int lane = threadIdx.x & 31;
    if (d >= NN) return;
    int c0 = lane * 8;

    float4 xr0 = *(const float4*)&xr[d * 256 + c0];
    float4 xr1 = *(const float4*)&xr[d * 256 + c0 + 4];
    float4 we0 = *(const float4*)&We[c0];
    float4 we1 = *(const float4*)&We[c0 + 4];
    float4 at0 = *(const float4*)&att[c0];
    float4 at1 = *(const float4*)&att[c0 + 4];

    int beg = rowptr[d], end = rowptr[d + 1];
    float m = -INFINITY, den = 0.f;
    float acc[8] = {0.f, 0.f, 0.f, 0.f, 0.f, 0.f, 0.f, 0.f};

    for (int p = beg; p < end; p++) {
        int e = coleid[p];
        int s = src[e];
        float ea = eattr[e];
        float4 a0 = *(const float4*)&xl[s * 256 + c0];
        float4 a1 = *(const float4*)&xl[s * 256 + c0 + 4];

        float v0 = a0.x + xr0.x + ea * we0.x;
        float v1 = a0.y + xr0.y + ea * we0.y;
        float v2 = a0.z + xr0.z + ea * we0.z;
        float v3 = a0.w + xr0.w + ea * we0.w;
        float v4 = a1.x + xr1.x + ea * we1.x;
        float v5 = a1.y + xr1.y + ea * we1.y;
        float v6 = a1.z + xr1.z + ea * we1.z;
        float v7 = a1.w + xr1.w + ea * we1.w;
        v0 = (v0 > 0.f) ? v0 : 0.2f * v0;
        v1 = (v1 > 0.f) ? v1 : 0.2f * v1;
        v2 = (v2 > 0.f) ? v2 : 0.2f * v2;
        v3 = (v3 > 0.f) ? v3 : 0.2f * v3;
        v4 = (v4 > 0.f) ? v4 : 0.2f * v4;
        v5 = (v5 > 0.f) ? v5 : 0.2f * v5;
        v6 = (v6 > 0.f) ? v6 : 0.2f * v6;
        v7 = (v7 > 0.f) ? v7 : 0.2f * v7;

        float part = v0 * at0.x + v1 * at0.y + v2 * at0.z + v3 * at0.w
                   + v4 * at1.x + v5 * at1.y + v6 * at1.z + v7 * at1.w;
        // reduce over the 8-lane head group
        part += __shfl_xor_sync(0xffffffffu, part, 1);
        part += __shfl_xor_sync(0xffffffffu, part, 2);
        part += __shfl_xor_sync(0xffffffffu, part, 4);
        float l = part;

        float m_new = fmaxf(m, l);
        float scale = __expf(m - m_new);     // exp(-inf)=0 on first edge
        float w = __expf(l - m_new);
        den = den * scale + w;
        acc[0] = acc[0] * scale + w * a0.x;
        acc[1] = acc[1] * scale + w * a0.y;
        acc[2] = acc[2] * scale + w * a0.z;
        acc[3] = acc[3] * scale + w * a0.w;
        acc[4] = acc[4] * scale + w * a1.x;
        acc[5] = acc[5] * scale + w * a1.y;
        acc[6] = acc[6] * scale + w * a1.z;
        acc[7] = acc[7] * scale + w * a1.w;
        m = m_new;
    }

    float inv = 1.f / (den + 1e-16f);
    float4 b0 = *(const float4*)&bias[c0];
    float4 b1 = *(const float4*)&bias[c0 + 4];
    float4 o0 = make_float4(fmaxf(acc[0] * inv + b0.x, 0.f),
                            fmaxf(acc[1] * inv + b0.y, 0.f),
                            fmaxf(acc[2] * inv + b0.z, 0.f),
                            fmaxf(acc[3] * inv + b0.w, 0.f));
    float4 o1 = make_float4(fmaxf(acc[4] * inv + b1.x, 0.f),
                            fmaxf(acc[5] * inv + b1.y, 0.f),
                            fmaxf(acc[6] * inv + b1.z, 0.f),
                            fmaxf(acc[7] * inv + b1.w, 0.f));
    *(float4*)&h_out[d * 256 + c0] = o0;
    *(float4*)&h_out[d * 256 + c0 + 4] = o1;
}

// ---------------- mean pool (batch sorted) ----------------
__global__ void pool_kernel(const float* __restrict__ h, const int* __restrict__ batch,
                            float* __restrict__ sums, float* __restrict__ cnt) {
    int c = threadIdx.x;
    int n0 = blockIdx.x * 64;
    if (n0 >= NN) return;
    int cur = batch[n0];
    float acc = 0.f, fc = 0.f;
    for (int i = 0; i < 64; i++) {
        int node = n0 + i;
        if (node >= NN) break;
        int b = batch[node];
        if (b != cur) {
            atomicAdd(&sums[cur * 256 + c], acc);
            if (c == 0) atomicAdd(&cnt[cur], fc);
            acc = 0.f; fc = 0.f; cur = b;
        }
        acc += h[node * 256 + c];
        fc += 1.f;
    }
    atomicAdd(&sums[cur * 256 + c], acc);
    if (c == 0) atomicAdd(&cnt[cur], fc);
}

// ---------------- MLP head ----------------
__global__ void head_kernel(const float* __restrict__ sums, const float* __restrict__ cnt,
                            const float* __restrict__ Wp1, const float* __restrict__ bp1,
                            const float* __restrict__ lng, const float* __restrict__ lnb,
                            const float* __restrict__ Wp2, const float* __restrict__ bp2,
                            const float* __restrict__ Wh, const float* __restrict__ bh,
                            float* __restrict__ out) {
    __shared__ float pool[256];
    __shared__ float pbuf[128];
    __shared__ float qbuf[64];
    __shared__ float redbuf[4];
    int g = blockIdx.x, t = threadIdx.x;
    float cn = fmaxf(cnt[g], 1.f);
    pool[t] = sums[g * 256 + t] / cn;
    pool[t + 128] = sums[g * 256 + 128 + t] / cn;
    __syncthreads();

    float acc = bp1[t];
#pragma unroll 4
    for (int k = 0; k < 256; k++) acc += pool[k] * Wp1[k * 128 + t];

    float s = acc;
#pragma unroll
    for (int o = 16; o > 0; o >>= 1) s += __shfl_xor_sync(0xffffffffu, s, o);
    if ((t & 31) == 0) redbuf[t >> 5] = s;
    __syncthreads();
    float mu = (redbuf[0] + redbuf[1] + redbuf[2] + redbuf[3]) * (1.f / 128.f);
    __syncthreads();

    float dv = (acc - mu) * (acc - mu);
#pragma unroll
    for (int o = 16; o > 0; o >>= 1) dv += __shfl_xor_sync(0xffffffffu, dv, o);
    if ((t & 31) == 0) redbuf[t >> 5] = dv;
    __syncthreads();
    float var = (redbuf[0] + redbuf[1] + redbuf[2] + redbuf[3]) * (1.f / 128.f);

    float v = (acc - mu) * rsqrtf(var + 1e-5f) * lng[t] + lnb[t];
    pbuf[t] = fmaxf(v, 0.f);
    __syncthreads();

    if (t < 64) {
        float a = bp2[t];
#pragma unroll 4
        for (int k = 0; k < 128; k++) a += pbuf[k] * Wp2[k * 64 + t];
        qbuf[t] = fmaxf(a, 0.f);
    }
    __syncthreads();

    if (t < 32) {
        float a = qbuf[t] * Wh[t] + qbuf[t + 32] * Wh[t + 32];
#pragma unroll
        for (int o = 16; o > 0; o >>= 1) a += __shfl_xor_sync(0xffffffffu, a, o);
        if (t == 0) out[g] = a + bh[0];
    }
}

// ---------------- launch ----------------
static const int MMA_SMEM = 2 * 2 * STAGEF * 4;

extern "C" void kernel_launch(void* const* d_in, const int* in_sizes, int n_in,
                              void* d_out, int out_size) {
    const float* x       = (const float*)d_in[0];
    const float* eattr   = (const float*)d_in[1];
    const int*   src     = (const int*)d_in[2];
    const int*   dst     = (const int*)d_in[3];
    const int*   batch   = (const int*)d_in[4];
    const float* W_enc   = (const float*)d_in[5];
    const float* b_enc   = (const float*)d_in[6];
    const float* g1_Wl   = (const float*)d_in[7];
    const float* g1_bl   = (const float*)d_in[8];
    const float* g1_Wr   = (const float*)d_in[9];
    const float* g1_br   = (const float*)d_in[10];
    const float* g1_We   = (const float*)d_in[11];
    const float* g1_att  = (const float*)d_in[12];
    const float* g1_bias = (const float*)d_in[13];
    const float* g2_Wl   = (const float*)d_in[14];
    const float* g2_bl   = (const float*)d_in[15];
    const float* g2_Wr   = (const float*)d_in[16];
    const float* g2_br   = (const float*)d_in[17];
    const float* g2_We   = (const float*)d_in[18];
    const float* g2_att  = (const float*)d_in[19];
    const float* g2_bias = (const float*)d_in[20];
    const float* W_p1    = (const float*)d_in[21];
    const float* b_p1    = (const float*)d_in[22];
    const float* ln_g    = (const float*)d_in[23];
    const float* ln_b    = (const float*)d_in[24];
    const float* W_p2    = (const float*)d_in[25];
    const float* b_p2    = (const float*)d_in[26];
    const float* W_head  = (const float*)d_in[27];
    const float* b_head  = (const float*)d_in[28];
    float* out = (float*)d_out;

    float *h0, *xl, *xr, *h1, *sums, *cnt, *wt;
    int *rowptr, *cursor, *coleid, *bsums;
    cudaGetSymbolAddress((void**)&h0,     g_h0);
    cudaGetSymbolAddress((void**)&xl,     g_xl);
    cudaGetSymbolAddress((void**)&xr,     g_xr);
    cudaGetSymbolAddress((void**)&h1,     g_h1);
    cudaGetSymbolAddress((void**)&sums,   g_sums);
    cudaGetSymbolAddress((void**)&cnt,    g_cnt);
    cudaGetSymbolAddress((void**)&wt,     g_wt);
    cudaGetSymbolAddress((void**)&rowptr, g_rowptr);
    cudaGetSymbolAddress((void**)&cursor, g_cursor);
    cudaGetSymbolAddress((void**)&coleid, g_coleid);
    cudaGetSymbolAddress((void**)&bsums,  g_bsums);

    cudaFuncSetAttribute(mma_lr_kernel<64>,  cudaFuncAttributeMaxDynamicSharedMemorySize, MMA_SMEM);
    cudaFuncSetAttribute(mma_lr_kernel<256>, cudaFuncAttributeMaxDynamicSharedMemorySize, MMA_SMEM);

    const int MT = (NN + 127) / 128;
    dim3 gemm_grid(MT, 4);
    const int NB_SCAN = (NN + 1023) / 1024;     // 98
    const int EW_GRID = (NN + 7) / 8;           // warp per node

    // ---- CSR build over dst (shared by both layers) ----
    fill_int_kernel<<<(NN + 255) / 256, 256>>>(cursor, 0, NN);
    hist_kernel<<<(EE + 255) / 256, 256>>>(dst, cursor);
    scan1_kernel<<<NB_SCAN, 1024>>>(cursor, rowptr, bsums);
    scan2_kernel<<<1, 128>>>(bsums, NB_SCAN);
    scan3_kernel<<<NB_SCAN, 1024>>>(rowptr, bsums, cursor);
    cursor_kernel<<<(NN + 255) / 256, 256>>>(rowptr, cursor);
    fillcol_kernel<<<(EE + 255) / 256, 256>>>(dst, cursor, coleid);

    // encoder
    enc_kernel<<<(NN * 64 + 255) / 256, 256>>>(x, W_enc, b_enc, h0);

    // GAT layer 1 (K=64)
    build_wt_kernel<<<(512 * 64 + 255) / 256, 256>>>(g1_Wl, g1_Wr, wt, 64);
    mma_lr_kernel<64><<<gemm_grid, 256, MMA_SMEM>>>(h0, wt, g1_bl, g1_br, xl, xr, NN);
    edge_fused_kernel<<<EW_GRID, 256>>>(xl, xr, eattr, g1_We, g1_att, src,
                                        rowptr, coleid, g1_bias, h1);

    // GAT layer 2 (K=256)
    build_wt_kernel<<<(512 * 256 + 255) / 256, 256>>>(g2_Wl, g2_Wr, wt, 256);
    mma_lr_kernel<256><<<gemm_grid, 256, MMA_SMEM>>>(h1, wt, g2_bl, g2_br, xl, xr, NN);
    edge_fused_kernel<<<EW_GRID, 256>>>(xl, xr, eattr, g2_We, g2_att, src,
                                        rowptr, coleid, g2_bias, h1);

    // pool + head
    fill_kernel<<<(GG * 256 + 255) / 256, 256>>>(sums, 0.f, GG * 256);
    fill_kernel<<<1, 64>>>(cnt, 0.f, GG);
    pool_kernel<<<(NN + 63) / 64, 256>>>(h1, batch, sums, cnt);
    head_kernel<<<GG, 128>>>(sums, cnt, W_p1, b_p1, ln_g, ln_b, W_p2, b_p2, W_head, b_head, out);
}

// round 5
// speedup vs baseline: 2.6222x; 1.0471x over previous
#include <cuda_runtime.h>
#include <cuda_bf16.h>
#include <math.h>
#include <cstdint>

#define NN 100000
#define EE 400000
#define GG 64

// ---------------- scratch (device globals; no allocation allowed) ----------------
__device__ float g_h0[NN * 64];        // encoder output
__device__ float g_xl[NN * 256];       // source-side transform
__device__ float g_xr[NN * 256];       // target-side transform
__device__ float g_h1[NN * 256];       // layer output
__device__ float g_sums[GG * 256];     // pooled sums
__device__ float g_cnt[GG];            // node counts per graph
__device__ float g_wt[512 * 256];      // fused transposed weights [512 n-rows, K] K-major
// CSR over dst (built once per launch; dst shared by both layers)
__device__ int   g_rowptr[NN + 1];
__device__ int   g_cursor[NN];         // histogram counts, then write cursors
__device__ int   g_csrc[EE];           // src id per CSR slot
__device__ float g_cea[EE];            // edge attr per CSR slot
__device__ int   g_bsums[128];

// ---------------- small utils ----------------
__global__ void fill_kernel(float* p, float v, int n) {
    int i = blockIdx.x * blockDim.x + threadIdx.x;
    if (i < n) p[i] = v;
}
__global__ void fill_int_kernel(int* p, int v, int n) {
    int i = blockIdx.x * blockDim.x + threadIdx.x;
    if (i < n) p[i] = v;
}

__device__ __forceinline__ uint32_t cvt_tf32(float x) {
    uint32_t r;
    asm("cvt.rna.tf32.f32 %0, %1;" : "=r"(r) : "f"(x));
    return r;
}
__device__ __forceinline__ void mma_tf32_16x8x8(float* d, const uint32_t* a, const uint32_t* b) {
    asm volatile(
        "mma.sync.aligned.m16n8k8.row.col.f32.tf32.tf32.f32 "
        "{%0,%1,%2,%3}, {%4,%5,%6,%7}, {%8,%9}, {%0,%1,%2,%3};"
        : "+f"(d[0]), "+f"(d[1]), "+f"(d[2]), "+f"(d[3])
        : "r"(a[0]), "r"(a[1]), "r"(a[2]), "r"(a[3]), "r"(b[0]), "r"(b[1]));
}

// ---------------- CSR build over dst ----------------
__global__ void hist_kernel(const int* __restrict__ dst, int* __restrict__ cnts) {
    int e = blockIdx.x * blockDim.x + threadIdx.x;
    if (e < EE) atomicAdd(&cnts[dst[e]], 1);
}
__global__ void scan1_kernel(const int* __restrict__ cnts, int* __restrict__ rowptr,
                             int* __restrict__ bsums) {
    __shared__ int buf[2][1024];
    int b = blockIdx.x, t = threadIdx.x;
    int i = b * 1024 + t;
    buf[0][t] = (i < NN) ? cnts[i] : 0;
    __syncthreads();
    int cur = 0;
#pragma unroll
    for (int off = 1; off < 1024; off <<= 1) {
        int x = buf[cur][t];
        if (t >= off) x += buf[cur][t - off];
        buf[cur ^ 1][t] = x;
        cur ^= 1;
        __syncthreads();
    }
    int inc = buf[cur][t];
    if (i < NN) rowptr[i + 1] = inc;
    if (t == 1023) bsums[b] = inc;
}
__global__ void scan2_kernel(int* __restrict__ bsums, int nb) {
    __shared__ int buf[2][128];
    int t = threadIdx.x;
    int v = (t < nb) ? bsums[t] : 0;
    buf[0][t] = v;
    __syncthreads();
    int cur = 0;
#pragma unroll
    for (int off = 1; off < 128; off <<= 1) {
        int x = buf[cur][t];
        if (t >= off) x += buf[cur][t - off];
        buf[cur ^ 1][t] = x;
        cur ^= 1;
        __syncthreads();
    }
    if (t < nb) bsums[t] = buf[cur][t] - v;   // exclusive
}
// finalize rowptr and also seed cursor = final rowptr
__global__ void scan3_kernel(int* __restrict__ rowptr, const int* __restrict__ bsums,
                             int* __restrict__ cursor) {
    int b = blockIdx.x, t = threadIdx.x;
    int i = b * 1024 + t;
    if (i < NN) {
        int rp1 = rowptr[i + 1] + bsums[b];
        rowptr[i + 1] = rp1;
        if (i + 1 < NN) cursor[i + 1] = rp1;
    }
    if (i == 0) { rowptr[0] = 0; cursor[0] = 0; }
}
// scatter src + eattr into CSR order (removes indirection in the hot loop)
__global__ void fillcol_kernel(const int* __restrict__ dst, const int* __restrict__ src,
                               const float* __restrict__ eattr, int* __restrict__ cursor,
                               int* __restrict__ csrc, float* __restrict__ cea) {
    int e = blockIdx.x * blockDim.x + threadIdx.x;
    if (e >= EE) return;
    int pos = atomicAdd(&cursor[dst[e]], 1);
    csrc[pos] = src[e];
    cea[pos] = eattr[e];
}

// ---------------- tf32 MMA GEMM: [xl|xr] = X[n,K] @ WT[512,K]^T + bias ----------------
#define ROWPITCH 36
#define STAGEF (128 * ROWPITCH)

template <int K>
__global__ void __launch_bounds__(256, 1)
mma_lr_kernel(const float* __restrict__ X, const float* __restrict__ WT,
              const float* __restrict__ bl, const float* __restrict__ br,
              float* __restrict__ xl, float* __restrict__ xr, int n) {
    extern __shared__ float smf[];
    constexpr int NC = K / 32;

    int tid = threadIdx.x;
    int wid = tid >> 5, lane = tid & 31;
    int wm = wid & 1, wn = wid >> 1;
    int tg = lane >> 2, tig = lane & 3;
    int row0 = blockIdx.x * 128;
    int nbase = blockIdx.y * 128;

    float d[4][4][4];
#pragma unroll
    for (int i = 0; i < 4; i++)
#pragma unroll
        for (int j = 0; j < 4; j++)
#pragma unroll
            for (int q = 0; q < 4; q++) d[i][j][q] = 0.f;

    float4 abuf[4], bbuf[4];
    auto ldg_chunk = [&](int c) {
#pragma unroll
        for (int j = 0; j < 4; j++) {
            int i = tid + j * 256;
            int r = i >> 3, q = i & 7;
            int row = row0 + r;
            abuf[j] = (row < n) ? *(const float4*)&X[row * K + c * 32 + q * 4]
                                : make_float4(0.f, 0.f, 0.f, 0.f);
            bbuf[j] = *(const float4*)&WT[(nbase + r) * K + c * 32 + q * 4];
        }
    };
    auto sts_chunk = [&](int s) {
        float* As = smf + s * (2 * STAGEF);
        float* Bs = As + STAGEF;
#pragma unroll
        for (int j = 0; j < 4; j++) {
            int i = tid + j * 256;
            int r = i >> 3, q = i & 7;
            uint32_t* pa = (uint32_t*)&As[r * ROWPITCH + q * 4];
            pa[0] = cvt_tf32(abuf[j].x); pa[1] = cvt_tf32(abuf[j].y);
            pa[2] = cvt_tf32(abuf[j].z); pa[3] = cvt_tf32(abuf[j].w);
            uint32_t* pb = (uint32_t*)&Bs[r * ROWPITCH + q * 4];
            pb[0] = cvt_tf32(bbuf[j].x); pb[1] = cvt_tf32(bbuf[j].y);
            pb[2] = cvt_tf32(bbuf[j].z); pb[3] = cvt_tf32(bbuf[j].w);
        }
    };

    ldg_chunk(0);
    sts_chunk(0);
    __syncthreads();

    for (int c = 0; c < NC; c++) {
        int s = c & 1;
        if (c + 1 < NC) ldg_chunk(c + 1);

        const uint32_t* As = (const uint32_t*)(smf + s * (2 * STAGEF));
        const uint32_t* Bs = As + STAGEF;
#pragma unroll
        for (int ks = 0; ks < 4; ks++) {
            uint32_t a[4][4], b[4][2];
#pragma unroll
            for (int mt = 0; mt < 4; mt++) {
                const uint32_t* p = As + (wm * 64 + mt * 16 + tg) * ROWPITCH + ks * 8 + tig;
                a[mt][0] = p[0];
                a[mt][1] = p[8 * ROWPITCH];
                a[mt][2] = p[4];
                a[mt][3] = p[8 * ROWPITCH + 4];
            }
#pragma unroll
            for (int nt = 0; nt < 4; nt++) {
                const uint32_t* p = Bs + (wn * 32 + nt * 8 + tg) * ROWPITCH + ks * 8 + tig;
                b[nt][0] = p[0];
                b[nt][1] = p[4];
            }
#pragma unroll
            for (int mt = 0; mt < 4; mt++)
#pragma unroll
                for (int nt = 0; nt < 4; nt++)
                    mma_tf32_16x8x8(d[mt][nt], a[mt], b[nt]);
        }

        if (c + 1 < NC) {
            __syncthreads();
            sts_chunk((c + 1) & 1);
            __syncthreads();
        }
    }

    float* Y = (blockIdx.y < 2) ? xl : xr;
    const float* bias = (blockIdx.y < 2) ? bl : br;
    int colb = (blockIdx.y & 1) * 128;
#pragma unroll
    for (int mt = 0; mt < 4; mt++) {
        int r0 = row0 + wm * 64 + mt * 16 + tg;
#pragma unroll
        for (int nt = 0; nt < 4; nt++) {
            int col = colb + wn * 32 + nt * 8 + 2 * tig;
            float2 bv = *(const float2*)&bias[col];
            if (r0 < n)
                *(float2*)&Y[r0 * 256 + col] =
                    make_float2(d[mt][nt][0] + bv.x, d[mt][nt][1] + bv.y);
            if (r0 + 8 < n)
                *(float2*)&Y[(r0 + 8) * 256 + col] =
                    make_float2(d[mt][nt][2] + bv.x, d[mt][nt][3] + bv.y);
        }
    }
}

__global__ void build_wt_kernel(const float* __restrict__ Wl, const float* __restrict__ Wr,
                                float* __restrict__ WT, int K) {
    int idx = blockIdx.x * blockDim.x + threadIdx.x;
    if (idx >= 512 * K) return;
    int nrow = idx / K, k = idx - nrow * K;
    WT[idx] = (nrow < 256) ? Wl[k * 256 + nrow] : Wr[k * 256 + (nrow - 256)];
}

// ---------------- encoder ----------------
__global__ void enc_kernel(const float* __restrict__ x, const float* __restrict__ W,
                           const float* __restrict__ b, float* __restrict__ h0) {
    int idx = blockIdx.x * blockDim.x + threadIdx.x;
    if (idx >= NN * 64) return;
    int i = idx >> 6;
    int c = idx & 63;
    float acc = b[c];
#pragma unroll
    for (int k = 0; k < 8; k++) acc += x[i * 8 + k] * W[k * 64 + c];
    h0[idx] = fmaxf(acc, 0.f);
}

// ---------------- fused GAT aggregation: one warp per dst node, online softmax ----------------
// lane owns channels c0 = lane*8 .. +7 (8 lanes per head). Pipelined CSR walk:
// (src, ea) for slot p+1 prefetched while gathering slot p.
__global__ void __launch_bounds__(256)
edge_fused_kernel(const float* __restrict__ xl, const float* __restrict__ xr,
                  const float* __restrict__ We, const float* __restrict__ att,
                  const int* __restrict__ rowptr,
                  const int* __restrict__ csrc, const float* __restrict__ cea,
                  const float* __restrict__ bias, float* __restrict__ h_out) {
    int d = blockIdx.x * 8 + (threadIdx.x >> 5);
    int lane = threadIdx.x & 31;
    if (d >= NN) return;
    int c0 = lane * 8;

    float4 xr0 = *(const float4*)&xr[d * 256 + c0];
    float4 xr1 = *(const float4*)&xr[d * 256 + c0 + 4];
    float4 we0 = *(const float4*)&We[c0];
    float4 we1 = *(const float4*)&We[c0 + 4];
    float4 at0 = *(const float4*)&att[c0];
    float4 at1 = *(const float4*)&att[c0 + 4];

    int beg = rowptr[d], end = rowptr[d + 1];
    float m = -INFINITY, den = 0.f;
    float acc[8] = {0.f, 0.f, 0.f, 0.f, 0.f, 0.f, 0.f, 0.f};

    int s_nxt = 0; float ea_nxt = 0.f;
    if (beg < end) { s_nxt = csrc[beg]; ea_nxt = cea[beg]; }

    for (int p = beg; p < end; p++) {
        int s = s_nxt; float ea = ea_nxt;
        if (p + 1 < end) { s_nxt = csrc[p + 1]; ea_nxt = cea[p + 1]; }

        float4 a0 = *(const float4*)&xl[s * 256 + c0];
        float4 a1 = *(const float4*)&xl[s * 256 + c0 + 4];

        float v0 = a0.x + xr0.x + ea * we0.x;
        float v1 = a0.y + xr0.y + ea * we0.y;
        float v2 = a0.z + xr0.z + ea * we0.z;
        float v3 = a0.w + xr0.w + ea * we0.w;
        float v4 = a1.x + xr1.x + ea * we1.x;
        float v5 = a1.y + xr1.y + ea * we1.y;
        float v6 = a1.z + xr1.z + ea * we1.z;
        float v7 = a1.w + xr1.w + ea * we1.w;
        v0 = (v0 > 0.f) ? v0 : 0.2f * v0;
        v1 = (v1 > 0.f) ? v1 : 0.2f * v1;
        v2 = (v2 > 0.f) ? v2 : 0.2f * v2;
        v3 = (v3 > 0.f) ? v3 : 0.2f * v3;
        v4 = (v4 > 0.f) ? v4 : 0.2f * v4;
        v5 = (v5 > 0.f) ? v5 : 0.2f * v5;
        v6 = (v6 > 0.f) ? v6 : 0.2f * v6;
        v7 = (v7 > 0.f) ? v7 : 0.2f * v7;

        float part = v0 * at0.x + v1 * at0.y + v2 * at0.z + v3 * at0.w
                   + v4 * at1.x + v5 * at1.y + v6 * at1.z + v7 * at1.w;
        part += __shfl_xor_sync(0xffffffffu, part, 1);
        part += __shfl_xor_sync(0xffffffffu, part, 2);
        part += __shfl_xor_sync(0xffffffffu, part, 4);
        float l = part;

        float m_new = fmaxf(m, l);
        float scale = __expf(m - m_new);
        float w = __expf(l - m_new);
        den = den * scale + w;
        acc[0] = acc[0] * scale + w * a0.x;
        acc[1] = acc[1] * scale + w * a0.y;
        acc[2] = acc[2] * scale + w * a0.z;
        acc[3] = acc[3] * scale + w * a0.w;
        acc[4] = acc[4] * scale + w * a1.x;
        acc[5] = acc[5] * scale + w * a1.y;
        acc[6] = acc[6] * scale + w * a1.z;
        acc[7] = acc[7] * scale + w * a1.w;
        m = m_new;
    }

    float inv = 1.f / (den + 1e-16f);
    float4 b0 = *(const float4*)&bias[c0];
    float4 b1 = *(const float4*)&bias[c0 + 4];
    float4 o0 = make_float4(fmaxf(acc[0] * inv + b0.x, 0.f),
                            fmaxf(acc[1] * inv + b0.y, 0.f),
                            fmaxf(acc[2] * inv + b0.z, 0.f),
                            fmaxf(acc[3] * inv + b0.w, 0.f));
    float4 o1 = make_float4(fmaxf(acc[4] * inv + b1.x, 0.f),
                            fmaxf(acc[5] * inv + b1.y, 0.f),
                            fmaxf(acc[6] * inv + b1.z, 0.f),
                            fmaxf(acc[7] * inv + b1.w, 0.f));
    *(float4*)&h_out[d * 256 + c0] = o0;
    *(float4*)&h_out[d * 256 + c0 + 4] = o1;
}

// ---------------- mean pool (batch sorted) ----------------
__global__ void pool_kernel(const float* __restrict__ h, const int* __restrict__ batch,
                            float* __restrict__ sums, float* __restrict__ cnt) {
    int c = threadIdx.x;
    int n0 = blockIdx.x * 64;
    if (n0 >= NN) return;
    int cur = batch[n0];
    float acc = 0.f, fc = 0.f;
    for (int i = 0; i < 64; i++) {
        int node = n0 + i;
        if (node >= NN) break;
        int b = batch[node];
        if (b != cur) {
            atomicAdd(&sums[cur * 256 + c], acc);
            if (c == 0) atomicAdd(&cnt[cur], fc);
            acc = 0.f; fc = 0.f; cur = b;
        }
        acc += h[node * 256 + c];
        fc += 1.f;
    }
    atomicAdd(&sums[cur * 256 + c], acc);
    if (c == 0) atomicAdd(&cnt[cur], fc);
}

// ---------------- MLP head ----------------
__global__ void head_kernel(const float* __restrict__ sums, const float* __restrict__ cnt,
                            const float* __restrict__ Wp1, const float* __restrict__ bp1,
                            const float* __restrict__ lng, const float* __restrict__ lnb,
                            const float* __restrict__ Wp2, const float* __restrict__ bp2,
                            const float* __restrict__ Wh, const float* __restrict__ bh,
                            float* __restrict__ out) {
    __shared__ float pool[256];
    __shared__ float pbuf[128];
    __shared__ float qbuf[64];
    __shared__ float redbuf[4];
    int g = blockIdx.x, t = threadIdx.x;
    float cn = fmaxf(cnt[g], 1.f);
    pool[t] = sums[g * 256 + t] / cn;
    pool[t + 128] = sums[g * 256 + 128 + t] / cn;
    __syncthreads();

    float acc = bp1[t];
#pragma unroll 4
    for (int k = 0; k < 256; k++) acc += pool[k] * Wp1[k * 128 + t];

    float s = acc;
#pragma unroll
    for (int o = 16; o > 0; o >>= 1) s += __shfl_xor_sync(0xffffffffu, s, o);
    if ((t & 31) == 0) redbuf[t >> 5] = s;
    __syncthreads();
    float mu = (redbuf[0] + redbuf[1] + redbuf[2] + redbuf[3]) * (1.f / 128.f);
    __syncthreads();

    float dv = (acc - mu) * (acc - mu);
#pragma unroll
    for (int o = 16; o > 0; o >>= 1) dv += __shfl_xor_sync(0xffffffffu, dv, o);
    if ((t & 31) == 0) redbuf[t >> 5] = dv;
    __syncthreads();
    float var = (redbuf[0] + redbuf[1] + redbuf[2] + redbuf[3]) * (1.f / 128.f);

    float v = (acc - mu) * rsqrtf(var + 1e-5f) * lng[t] + lnb[t];
    pbuf[t] = fmaxf(v, 0.f);
    __syncthreads();

    if (t < 64) {
        float a = bp2[t];
#pragma unroll 4
        for (int k = 0; k < 128; k++) a += pbuf[k] * Wp2[k * 64 + t];
        qbuf[t] = fmaxf(a, 0.f);
    }
    __syncthreads();

    if (t < 32) {
        float a = qbuf[t] * Wh[t] + qbuf[t + 32] * Wh[t + 32];
#pragma unroll
        for (int o = 16; o > 0; o >>= 1) a += __shfl_xor_sync(0xffffffffu, a, o);
        if (t == 0) out[g] = a + bh[0];
    }
}

// ---------------- launch ----------------
static const int MMA_SMEM = 2 * 2 * STAGEF * 4;

extern "C" void kernel_launch(void* const* d_in, const int* in_sizes, int n_in,
                              void* d_out, int out_size) {
    const float* x       = (const float*)d_in[0];
    const float* eattr   = (const float*)d_in[1];
    const int*   src     = (const int*)d_in[2];
    const int*   dst     = (const int*)d_in[3];
    const int*   batch   = (const int*)d_in[4];
    const float* W_enc   = (const float*)d_in[5];
    const float* b_enc   = (const float*)d_in[6];
    const float* g1_Wl   = (const float*)d_in[7];
    const float* g1_bl   = (const float*)d_in[8];
    const float* g1_Wr   = (const float*)d_in[9];
    const float* g1_br   = (const float*)d_in[10];
    const float* g1_We   = (const float*)d_in[11];
    const float* g1_att  = (const float*)d_in[12];
    const float* g1_bias = (const float*)d_in[13];
    const float* g2_Wl   = (const float*)d_in[14];
    const float* g2_bl   = (const float*)d_in[15];
    const float* g2_Wr   = (const float*)d_in[16];
    const float* g2_br   = (const float*)d_in[17];
    const float* g2_We   = (const float*)d_in[18];
    const float* g2_att  = (const float*)d_in[19];
    const float* g2_bias = (const float*)d_in[20];
    const float* W_p1    = (const float*)d_in[21];
    const float* b_p1    = (const float*)d_in[22];
    const float* ln_g    = (const float*)d_in[23];
    const float* ln_b    = (const float*)d_in[24];
    const float* W_p2    = (const float*)d_in[25];
    const float* b_p2    = (const float*)d_in[26];
    const float* W_head  = (const float*)d_in[27];
    const float* b_head  = (const float*)d_in[28];
    float* out = (float*)d_out;

    float *h0, *xl, *xr, *h1, *sums, *cnt, *wt, *cea;
    int *rowptr, *cursor, *csrc, *bsums;
    cudaGetSymbolAddress((void**)&h0,     g_h0);
    cudaGetSymbolAddress((void**)&xl,     g_xl);
    cudaGetSymbolAddress((void**)&xr,     g_xr);
    cudaGetSymbolAddress((void**)&h1,     g_h1);
    cudaGetSymbolAddress((void**)&sums,   g_sums);
    cudaGetSymbolAddress((void**)&cnt,    g_cnt);
    cudaGetSymbolAddress((void**)&wt,     g_wt);
    cudaGetSymbolAddress((void**)&rowptr, g_rowptr);
    cudaGetSymbolAddress((void**)&cursor, g_cursor);
    cudaGetSymbolAddress((void**)&csrc,   g_csrc);
    cudaGetSymbolAddress((void**)&cea,    g_cea);
    cudaGetSymbolAddress((void**)&bsums,  g_bsums);

    cudaFuncSetAttribute(mma_lr_kernel<64>,  cudaFuncAttributeMaxDynamicSharedMemorySize, MMA_SMEM);
    cudaFuncSetAttribute(mma_lr_kernel<256>, cudaFuncAttributeMaxDynamicSharedMemorySize, MMA_SMEM);

    const int MT = (NN + 127) / 128;
    dim3 gemm_grid(MT, 4);
    const int NB_SCAN = (NN + 1023) / 1024;
    const int EW_GRID = (NN + 7) / 8;

    // Launch order puts mma_lr<64> at index 5 (ncu captures -s 5 -c 1).
    enc_kernel<<<(NN * 64 + 255) / 256, 256>>>(x, W_enc, b_enc, h0);                  // 0
    build_wt_kernel<<<(512 * 64 + 255) / 256, 256>>>(g1_Wl, g1_Wr, wt, 64);           // 1
    fill_int_kernel<<<(NN + 255) / 256, 256>>>(cursor, 0, NN);                        // 2
    hist_kernel<<<(EE + 255) / 256, 256>>>(dst, cursor);                              // 3
    scan1_kernel<<<NB_SCAN, 1024>>>(cursor, rowptr, bsums);                           // 4
    mma_lr_kernel<64><<<gemm_grid, 256, MMA_SMEM>>>(h0, wt, g1_bl, g1_br, xl, xr, NN);// 5 <- profiled
    scan2_kernel<<<1, 128>>>(bsums, NB_SCAN);                                         // 6
    scan3_kernel<<<NB_SCAN, 1024>>>(rowptr, bsums, cursor);                           // 7
    fillcol_kernel<<<(EE + 255) / 256, 256>>>(dst, src, eattr, cursor, csrc, cea);    // 8

    edge_fused_kernel<<<EW_GRID, 256>>>(xl, xr, g1_We, g1_att,
                                        rowptr, csrc, cea, g1_bias, h1);

    build_wt_kernel<<<(512 * 256 + 255) / 256, 256>>>(g2_Wl, g2_Wr, wt, 256);
    mma_lr_kernel<256><<<gemm_grid, 256, MMA_SMEM>>>(h1, wt, g2_bl, g2_br, xl, xr, NN);
    edge_fused_kernel<<<EW_GRID, 256>>>(xl, xr, g2_We, g2_att,
                                        rowptr, csrc, cea, g2_bias, h1);

    fill_kernel<<<(GG * 256 + 255) / 256, 256>>>(sums, 0.f, GG * 256);
    fill_kernel<<<1, 64>>>(cnt, 0.f, GG);
    pool_kernel<<<(NN + 63) / 64, 256>>>(h1, batch, sums, cnt);
    head_kernel<<<GG, 128>>>(sums, cnt, W_p1, b_p1, ln_g, ln_b, W_p2, b_p2, W_head, b_head, out);
}